// round 1
// baseline (speedup 1.0000x reference)
#include <cuda_runtime.h>
#include <cstdint>

// ---------------- problem constants ----------------
#define BB   16
#define DD   64
#define HH   768
#define NE   7
#define FEAT 776          // H + NE + 1
#define ROWS (BB*DD)      // 1024 utterances
#define PAIRS_PER_B (DD*(DD+1)/2)   // 2080
#define NPAIR (BB*PAIRS_PER_B)      // 33280

// ---------------- device scratch (no allocs allowed) ----------------
__device__ float g_Wc[2*1552*2];   // combined expert weights: exp_w1[e] @ exp_w2[e], layout [e][j<1552][c]
__device__ float g_Ob[4];          // combined expert bias: exp_b1[e]@exp_w2[e] + exp_b2[e], layout [e*2+c]
__device__ float g_T[ROWS*12];     // per-utterance table: [G1(2) G2(2) O1(4:e0c0,e0c1,e1c0,e1c1) O2(4)]
__device__ float g_spk[ROWS];      // speaker ids as float

// ---------------- kernel 0: speaker id dtype-sniff + convert ----------------
// speaker_ids may be int64 or int32 on disk (values in {0,1}).
// If int64: odd 32-bit words of the first 1024 words are all zero (high halves).
// If int32: those words are random 0/1 -> some nonzero.
__global__ void spk_kernel(const void* spk_raw) {
    const unsigned int* u = (const unsigned int*)spk_raw;
    __shared__ int is64;
    if (threadIdx.x == 0) is64 = 1;
    __syncthreads();
    for (int i = threadIdx.x * 2 + 1; i < ROWS; i += 2 * blockDim.x) {
        if (u[i] != 0u) is64 = 0;
    }
    __syncthreads();
    bool w64 = (is64 != 0);
    for (int i = threadIdx.x; i < ROWS; i += blockDim.x) {
        unsigned int v = w64 ? u[2 * i] : u[i];
        g_spk[i] = (float)v;
    }
}

// ---------------- kernel 1: fold expert layers (linear!) ----------------
// Wc[e][j][c] = sum_k exp_w1[e][j][k] * exp_w2[e][k][c]
// Ob[e][c]    = sum_k exp_b1[e][k]    * exp_w2[e][k][c] + exp_b2[e][c]
// One warp per output row j (2 experts x 1552 rows = 3104 warps) + 4 warps for Ob.
__global__ void wc_kernel(const float* __restrict__ w1, const float* __restrict__ b1,
                          const float* __restrict__ w2, const float* __restrict__ b2) {
    int w = (blockIdx.x * blockDim.x + threadIdx.x) >> 5;
    int lane = threadIdx.x & 31;
    if (w < 2 * 1552) {
        int e = w / 1552, j = w % 1552;
        const float* a  = w1 + ((size_t)e * 1552 + j) * 256;
        const float* wb = w2 + e * 512;
        float a0 = 0.f, a1 = 0.f;
        #pragma unroll 4
        for (int k = lane; k < 256; k += 32) {
            float x = a[k];
            a0 += x * wb[k * 2 + 0];
            a1 += x * wb[k * 2 + 1];
        }
        #pragma unroll
        for (int off = 16; off; off >>= 1) {
            a0 += __shfl_down_sync(0xffffffffu, a0, off);
            a1 += __shfl_down_sync(0xffffffffu, a1, off);
        }
        if (lane == 0) {
            g_Wc[(e * 1552 + j) * 2 + 0] = a0;
            g_Wc[(e * 1552 + j) * 2 + 1] = a1;
        }
    } else if (w < 2 * 1552 + 4) {
        int idx = w - 2 * 1552;
        int e = idx >> 1, c = idx & 1;
        float s = 0.f;
        for (int k = lane; k < 256; k += 32)
            s += b1[e * 256 + k] * w2[e * 512 + k * 2 + c];
        #pragma unroll
        for (int off = 16; off; off >>= 1)
            s += __shfl_down_sync(0xffffffffu, s, off);
        if (lane == 0) g_Ob[idx] = s + b2[e * 2 + c];
    }
}

// ---------------- kernel 2: per-utterance table + emotion head ----------------
// For each row i (block): emotion_pred[i] = pooled[i]@emo_w + emo_b  (7)
// T[i][0:2]  = conc[i] @ gate_w[0:776]     (G1)
// T[i][2:4]  = conc[i] @ gate_w[776:1552]  (G2)
// T[i][4:8]  = conc[i] @ Wc[e][0:776][c]   (O1, idx=e*2+c)
// T[i][8:12] = conc[i] @ Wc[e][776:1552][c](O2)
// conc[i] = [pooled[i](768), emotion_pred[i](7), spk[i](1)]
__global__ void table_kernel(const float* __restrict__ pooled,
                             const float* __restrict__ emo_w,
                             const float* __restrict__ emo_b,
                             const float* __restrict__ gate_w,
                             float* __restrict__ out_emo) {
    int i = blockIdx.x;
    const float* row = pooled + (size_t)i * HH;
    int tid = threadIdx.x;
    int lane = tid & 31, warp = tid >> 5;

    float acc[19];
    #pragma unroll
    for (int m = 0; m < 19; m++) acc[m] = 0.f;

    for (int j = tid; j < HH; j += 256) {
        float x = row[j];
        #pragma unroll
        for (int c = 0; c < 7; c++) acc[c] += x * emo_w[j * 7 + c];
        acc[7]  += x * gate_w[j * 2 + 0];
        acc[8]  += x * gate_w[j * 2 + 1];
        acc[9]  += x * gate_w[(776 + j) * 2 + 0];
        acc[10] += x * gate_w[(776 + j) * 2 + 1];
        #pragma unroll
        for (int idx = 0; idx < 4; idx++) {
            int e = idx >> 1, c = idx & 1;
            acc[11 + idx] += x * g_Wc[(e * 1552 + j) * 2 + c];
            acc[15 + idx] += x * g_Wc[(e * 1552 + 776 + j) * 2 + c];
        }
    }

    // warp reduce all 19
    #pragma unroll
    for (int off = 16; off; off >>= 1) {
        #pragma unroll
        for (int m = 0; m < 19; m++)
            acc[m] += __shfl_down_sync(0xffffffffu, acc[m], off);
    }

    __shared__ float wsum[8][19];
    __shared__ float ep[7];
    if (lane == 0) {
        #pragma unroll
        for (int m = 0; m < 19; m++) wsum[warp][m] = acc[m];
    }
    __syncthreads();

    if (warp == 0) {
        float s = 0.f;
        if (lane < 19) {
            #pragma unroll
            for (int w = 0; w < 8; w++) s += wsum[w][lane];
        }
        if (lane < 7) {
            float v = s + emo_b[lane];
            ep[lane] = v;
            out_emo[(size_t)i * 7 + lane] = v;
        }
        __syncwarp();
        if (lane >= 7 && lane < 19) {
            int m = lane;
            float v = s;
            float spkv = g_spk[i];
            #pragma unroll
            for (int f = 768; f < 776; f++) {
                float xf = (f == 775) ? spkv : ep[f - 768];
                float w;
                if (m < 9)        w = gate_w[f * 2 + (m - 7)];
                else if (m < 11)  w = gate_w[(776 + f) * 2 + (m - 9)];
                else if (m < 15) { int idx = m - 11; w = g_Wc[(((idx >> 1) * 1552 + f)) * 2 + (idx & 1)]; }
                else             { int idx = m - 15; w = g_Wc[(((idx >> 1) * 1552 + 776 + f)) * 2 + (idx & 1)]; }
                v += xf * w;
            }
            g_T[i * 12 + (m - 7)] = v;
        }
    }
}

// ---------------- kernel 3: pair combine ----------------
// pair p in batch b: end-major tril order; q = p % 2080; end from inverse triangle; t = q - end(end+1)/2
// gating[e] = G1[t][e] + G2[end][e] + gate_b[e]
// o[e][c]   = O1[t][e,c] + O2[end][e,c] + Ob[e,c]
// cause[c]  = g0*o[0][c] + g1*o[1][c]
__global__ void pair_kernel(const float* __restrict__ gate_b,
                            float* __restrict__ out_cause) {
    int p = blockIdx.x * blockDim.x + threadIdx.x;
    if (p >= NPAIR) return;
    int b = p / PAIRS_PER_B;
    int q = p - b * PAIRS_PER_B;
    int end = (int)((sqrtf(8.f * (float)q + 1.f) - 1.f) * 0.5f);
    while ((end + 1) * (end + 2) / 2 <= q) end++;
    while (end * (end + 1) / 2 > q) end--;
    int t = q - end * (end + 1) / 2;

    const float* Tt = g_T + (b * DD + t)   * 12;
    const float* Te = g_T + (b * DD + end) * 12;

    float g0 = Tt[0] + Te[2] + gate_b[0];
    float g1 = Tt[1] + Te[3] + gate_b[1];

    float o00 = Tt[4] + Te[8]  + g_Ob[0];
    float o01 = Tt[5] + Te[9]  + g_Ob[1];
    float o10 = Tt[6] + Te[10] + g_Ob[2];
    float o11 = Tt[7] + Te[11] + g_Ob[3];

    out_cause[(size_t)p * 2 + 0] = g0 * o00 + g1 * o10;
    out_cause[(size_t)p * 2 + 1] = g0 * o01 + g1 * o11;
}

// ---------------- launch ----------------
extern "C" void kernel_launch(void* const* d_in, const int* in_sizes, int n_in,
                              void* d_out, int out_size) {
    const float* pooled  = (const float*)d_in[0];
    const void*  spk     = d_in[1];
    const float* emo_w   = (const float*)d_in[2];
    const float* emo_b   = (const float*)d_in[3];
    const float* gate_w  = (const float*)d_in[4];
    const float* gate_b  = (const float*)d_in[5];
    const float* exp_w1  = (const float*)d_in[6];
    const float* exp_b1  = (const float*)d_in[7];
    const float* exp_w2  = (const float*)d_in[8];
    const float* exp_b2  = (const float*)d_in[9];
    float* out = (float*)d_out;

    spk_kernel<<<1, 256>>>(spk);
    wc_kernel<<<(2 * 1552 + 4 + 7) / 8, 256>>>(exp_w1, exp_b1, exp_w2, exp_b2);
    table_kernel<<<ROWS, 256>>>(pooled, emo_w, emo_b, gate_w, out);
    pair_kernel<<<(NPAIR + 255) / 256, 256>>>(gate_b, out + ROWS * NE);
}